// round 16
// baseline (speedup 1.0000x reference)
#include <cuda_runtime.h>
#include <cuda_fp16.h>
#include <stdint.h>

#define MAXN 100000
#define MAXE 1600000
#define PAD  64
#define OUTD 256
#define MAXIN 128

// ---------------- scratch (device globals; no runtime allocation) ----------------
__device__ int    g_cnt[MAXN];
__device__ int    g_csr[(size_t)MAXN * PAD];
__device__ float  g_dinv[MAXN];
__device__ __half g_xh[(size_t)MAXN * MAXIN];    // fp16 copy of x
__device__ __half g_axh[(size_t)MAXN * MAXIN];   // A_hat @ X (fp16)
__device__ __half g_h1h[(size_t)MAXN * OUTD];    // relu((AX)W1 + b1)
__device__ __half g_ah1[(size_t)MAXN * OUTD];    // A_hat @ H1
__device__ __half g_idenh[(size_t)MAXN * OUTD];  // X@Wp + bp
__device__ __half g_W1h[MAXIN * OUTD];
__device__ __half g_W2h[OUTD * OUTD];
__device__ __half g_Wph[MAXIN * OUTD];

// ---------------- small setup kernels ----------------
__global__ void zero_cnt_kernel(int n) {
    int i = blockIdx.x * blockDim.x + threadIdx.x;
    if (i < n) g_cnt[i] = 0;
}

__global__ void f2h_kernel(const float* __restrict__ src, __half* __restrict__ dst, int count4) {
    int i = blockIdx.x * blockDim.x + threadIdx.x;
    if (i < count4) {
        float4 v = *(const float4*)(src + 4 * (size_t)i);
        __half2 h0 = __floats2half2_rn(v.x, v.y);
        __half2 h1 = __floats2half2_rn(v.z, v.w);
        uint2 u; u.x = *(unsigned*)&h0; u.y = *(unsigned*)&h1;
        *(uint2*)(dst + 4 * (size_t)i) = u;
    }
}

// Build padded CSR grouped by destination. int64 vs int32 detection: if data is
// int64 the high dword of every 8-byte word is 0 (values < N); if int32 the high
// dwords contain edge entries (nonzero across 16 words w.h.p.).
__global__ void fill_csr_kernel(const void* __restrict__ edge, int E) {
    const unsigned long long* p64 = (const unsigned long long*)edge;
    unsigned long long hi = 0ull;
#pragma unroll
    for (int i = 0; i < 16; i++) hi |= (p64[i] >> 32);
    const bool is64 = (hi == 0ull);
    const long long* e64 = (const long long*)edge;
    const int*       e32 = (const int*)edge;

    for (int e = blockIdx.x * blockDim.x + threadIdx.x; e < E;
         e += gridDim.x * blockDim.x) {
        int s, d;
        if (is64) { s = (int)e64[e]; d = (int)e64[e + E]; }
        else      { s = e32[e];      d = e32[e + E]; }
        int slot = atomicAdd(&g_cnt[d], 1);
        if (slot < PAD) g_csr[(size_t)d * PAD + slot] = s;
    }
}

__global__ void dinv_kernel(int n) {
    int i = blockIdx.x * blockDim.x + threadIdx.x;
    if (i < n) g_dinv[i] = rsqrtf((float)(g_cnt[i] + 1));  // +1 self-loop
}

// ---------------- HGEMM via mma.sync: C = A[M,K] @ B[K,N], fp16 in, fp32 accum ----
// CTA tile 128x64, BK=32, 8 warps. Epilogue: +bias, +fp16 resid, relu, fp16/fp32 out.
#define GBM 128
#define GBN 64
#define GBK 32
#define A_STRIDE 40   // halfs per As row (32 + 8 pad)
#define B_STRIDE 72   // halfs per Bs row (64 + 8 pad)

template <bool RELU, bool RESID, bool HALF_OUT>
__global__ __launch_bounds__(256, 2)
void hgemm_kernel(const __half* __restrict__ A, const __half* __restrict__ B,
                  const float* __restrict__ bias, const __half* __restrict__ resid,
                  void* __restrict__ Cv, int M, int K, int N) {
    __shared__ __half As[GBM][A_STRIDE];
    __shared__ __half Bs[GBK][B_STRIDE];

    const int tid  = threadIdx.x;
    const int wid  = tid >> 5;
    const int lane = tid & 31;
    const int warpM = wid & 3;
    const int warpN = wid >> 2;
    const int rowBase = blockIdx.x * GBM;
    const int colBase = blockIdx.y * GBN;

    const int arow = tid >> 1;
    const int acg  = (tid & 1) * 16;
    const int brow = tid >> 3;
    const int bcg  = (tid & 7) * 8;

    const bool aok = (rowBase + arow) < M;
    const __half* Ap = A + (size_t)(rowBase + arow) * K + acg;

    const uint4 z4 = make_uint4(0, 0, 0, 0);
    uint4 pa0 = aok ? *(const uint4*)Ap       : z4;
    uint4 pa1 = aok ? *(const uint4*)(Ap + 8) : z4;
    uint4 pb0 = *(const uint4*)(B + (size_t)brow * N + colBase + bcg);

    float acc[2][4][4];
#pragma unroll
    for (int i = 0; i < 2; i++)
#pragma unroll
        for (int j = 0; j < 4; j++)
#pragma unroll
            for (int k = 0; k < 4; k++) acc[i][j][k] = 0.f;

    const uint32_t AsU = (uint32_t)__cvta_generic_to_shared(&As[0][0]);
    const uint32_t BsU = (uint32_t)__cvta_generic_to_shared(&Bs[0][0]);
    const uint32_t aLaneOff = (lane & 15) * (A_STRIDE * 2) + (lane >> 4) * 16;
    const uint32_t bLaneOff = (lane & 15) * (B_STRIDE * 2) + (lane >> 4) * 16;

    int k0 = 0;
    while (true) {
        *(uint4*)&As[arow][acg]     = pa0;
        *(uint4*)&As[arow][acg + 8] = pa1;
        *(uint4*)&Bs[brow][bcg]     = pb0;
        __syncthreads();

        k0 += GBK;
        const bool more = (k0 < K);
        if (more) {
            pa0 = aok ? *(const uint4*)(Ap + k0)     : z4;
            pa1 = aok ? *(const uint4*)(Ap + k0 + 8) : z4;
            pb0 = *(const uint4*)(B + (size_t)(k0 + brow) * N + colBase + bcg);
        }

#pragma unroll
        for (int ks = 0; ks < 2; ks++) {
            uint32_t a[2][4];
#pragma unroll
            for (int mi = 0; mi < 2; mi++) {
                uint32_t addr = AsU + (warpM * 32 + mi * 16) * (A_STRIDE * 2)
                              + ks * 32 + aLaneOff;
                asm volatile("ldmatrix.sync.aligned.m8n8.x4.shared.b16 {%0,%1,%2,%3}, [%4];"
                             : "=r"(a[mi][0]), "=r"(a[mi][1]), "=r"(a[mi][2]), "=r"(a[mi][3])
                             : "r"(addr));
            }
            uint32_t b[4][2];
#pragma unroll
            for (int np = 0; np < 2; np++) {
                uint32_t addr = BsU + (ks * 16) * (B_STRIDE * 2)
                              + (warpN * 32 + np * 16) * 2 + bLaneOff;
                uint32_t r0, r1, r2, r3;
                asm volatile("ldmatrix.sync.aligned.m8n8.x4.trans.shared.b16 {%0,%1,%2,%3}, [%4];"
                             : "=r"(r0), "=r"(r1), "=r"(r2), "=r"(r3)
                             : "r"(addr));
                b[np * 2][0] = r0; b[np * 2][1] = r1;
                b[np * 2 + 1][0] = r2; b[np * 2 + 1][1] = r3;
            }
#pragma unroll
            for (int mi = 0; mi < 2; mi++)
#pragma unroll
                for (int nt = 0; nt < 4; nt++) {
                    asm volatile(
                        "mma.sync.aligned.m16n8k16.row.col.f32.f16.f16.f32 "
                        "{%0,%1,%2,%3}, {%4,%5,%6,%7}, {%8,%9}, {%0,%1,%2,%3};"
                        : "+f"(acc[mi][nt][0]), "+f"(acc[mi][nt][1]),
                          "+f"(acc[mi][nt][2]), "+f"(acc[mi][nt][3])
                        : "r"(a[mi][0]), "r"(a[mi][1]), "r"(a[mi][2]), "r"(a[mi][3]),
                          "r"(b[nt][0]), "r"(b[nt][1]));
                }
        }

        if (!more) break;
        __syncthreads();
    }

    const int group = lane >> 2;
    const int tid4  = lane & 3;
#pragma unroll
    for (int mi = 0; mi < 2; mi++) {
#pragma unroll
        for (int nt = 0; nt < 4; nt++) {
            int col = colBase + warpN * 32 + nt * 8 + tid4 * 2;
            float bx = 0.f, by = 0.f;
            if (bias) { bx = bias[col]; by = bias[col + 1]; }
#pragma unroll
            for (int rh = 0; rh < 2; rh++) {
                int r = rowBase + warpM * 32 + mi * 16 + group + rh * 8;
                if (r >= M) continue;
                float v0 = acc[mi][nt][rh * 2 + 0] + bx;
                float v1 = acc[mi][nt][rh * 2 + 1] + by;
                if (RESID) {
                    __half2 q = *(const __half2*)(resid + (size_t)r * N + col);
                    float2 f = __half22float2(q);
                    v0 += f.x; v1 += f.y;
                }
                if (RELU) { v0 = fmaxf(v0, 0.f); v1 = fmaxf(v1, 0.f); }
                if (HALF_OUT) {
                    __half2 h = __floats2half2_rn(v0, v1);
                    *(__half2*)((__half*)Cv + (size_t)r * N + col) = h;
                } else {
                    *(float2*)((float*)Cv + (size_t)r * N + col) = make_float2(v0, v1);
                }
            }
        }
    }
}

// ---------------- pure aggregation: out = A_hat @ M  (fp16 in/out, fp32 accum) ----------------
// One warp per node; lane owns 4 consecutive cols of a `pitch`-wide row.
// colOff selects the 128-col slice (pitch 128: single pass; pitch 256: two passes).
__device__ __forceinline__ void h4_acc(uint2 v, float w, float* acc) {
    float2 f0 = __half22float2(*(__half2*)&v.x);
    float2 f1 = __half22float2(*(__half2*)&v.y);
    acc[0] = fmaf(w, f0.x, acc[0]); acc[1] = fmaf(w, f0.y, acc[1]);
    acc[2] = fmaf(w, f1.x, acc[2]); acc[3] = fmaf(w, f1.y, acc[3]);
}

__global__ __launch_bounds__(256)
void aggregate_kernel(const __half* __restrict__ src, __half* __restrict__ dst,
                      int n, int pitch, int colOff) {
    __shared__ int   shI[8][PAD];
    __shared__ float shW[8][PAD];

    const int wslot = threadIdx.x >> 5;
    const int w     = (blockIdx.x * blockDim.x + threadIdx.x) >> 5;
    const int lane  = threadIdx.x & 31;
    if (w >= n) return;

    const int col = colOff + lane * 4;
    const float di = g_dinv[w];

    int c = g_cnt[w];
    if (c > PAD) c = PAD;

    const int* ep = g_csr + (size_t)w * PAD;
#pragma unroll
    for (int r = 0; r < PAD / 32; r++) {
        int j = r * 32 + lane;
        if (j < c) {
            int s = ep[j];
            shI[wslot][j] = s;
            shW[wslot][j] = g_dinv[s] * di;
        }
    }
    __syncwarp();

    float acc[4] = {0.f, 0.f, 0.f, 0.f};
    h4_acc(*(const uint2*)(src + (size_t)w * pitch + col), di * di, acc);  // self-loop

    const int*   shi = shI[wslot];
    const float* shw = shW[wslot];
    int j = 0;
    for (; j + 4 <= c; j += 4) {
        int   s0 = shi[j],   s1 = shi[j+1], s2 = shi[j+2], s3 = shi[j+3];
        float w0 = shw[j],   w1 = shw[j+1], w2 = shw[j+2], w3 = shw[j+3];
        uint2 v0 = *(const uint2*)(src + (size_t)s0 * pitch + col);
        uint2 v1 = *(const uint2*)(src + (size_t)s1 * pitch + col);
        uint2 v2 = *(const uint2*)(src + (size_t)s2 * pitch + col);
        uint2 v3 = *(const uint2*)(src + (size_t)s3 * pitch + col);
        h4_acc(v0, w0, acc); h4_acc(v1, w1, acc);
        h4_acc(v2, w2, acc); h4_acc(v3, w3, acc);
    }
    for (; j < c; j++) {
        uint2 v = *(const uint2*)(src + (size_t)shi[j] * pitch + col);
        h4_acc(v, shw[j], acc);
    }

    __half2 h01 = __floats2half2_rn(acc[0], acc[1]);
    __half2 h23 = __floats2half2_rn(acc[2], acc[3]);
    uint2 u; u.x = *(unsigned*)&h01; u.y = *(unsigned*)&h23;
    *(uint2*)(dst + (size_t)w * pitch + col) = u;
}

// ---------------- launch ----------------
extern "C" void kernel_launch(void* const* d_in, const int* in_sizes, int n_in,
                              void* d_out, int out_size) {
    const float* x  = (const float*)d_in[0];
    const void*  ei = d_in[1];
    const float* W1 = (const float*)d_in[2];
    const float* b1 = (const float*)d_in[3];
    const float* W2 = (const float*)d_in[4];
    const float* b2 = (const float*)d_in[5];
    const float* Wp = (const float*)d_in[6];
    const float* bp = (const float*)d_in[7];
    float* out = (float*)d_out;

    int ind = in_sizes[2] / OUTD;     // W1 is [IN, 256]
    int n   = in_sizes[0] / ind;      // nodes
    int E   = in_sizes[1] / 2;        // edges
    if (n > MAXN) n = MAXN;
    if (E > MAXE) E = MAXE;

    __half *xh, *axh, *h1h, *ah1, *idenh, *W1h, *W2h, *Wph;
    cudaGetSymbolAddress((void**)&xh,    g_xh);
    cudaGetSymbolAddress((void**)&axh,   g_axh);
    cudaGetSymbolAddress((void**)&h1h,   g_h1h);
    cudaGetSymbolAddress((void**)&ah1,   g_ah1);
    cudaGetSymbolAddress((void**)&idenh, g_idenh);
    cudaGetSymbolAddress((void**)&W1h,   g_W1h);
    cudaGetSymbolAddress((void**)&W2h,   g_W2h);
    cudaGetSymbolAddress((void**)&Wph,   g_Wph);

    // 1. build padded CSR + degrees
    zero_cnt_kernel<<<(n + 255) / 256, 256>>>(n);
    fill_csr_kernel<<<(E + 255) / 256, 256>>>(ei, E);
    dinv_kernel<<<(n + 255) / 256, 256>>>(n);

    // 2. fp32 -> fp16 converts
    int xc4 = (n * ind) / 4;
    f2h_kernel<<<(xc4 + 255) / 256, 256>>>(x, xh, xc4);
    f2h_kernel<<<(ind * OUTD / 4 + 255) / 256, 256>>>(W1, W1h, ind * OUTD / 4);
    f2h_kernel<<<(ind * OUTD / 4 + 255) / 256, 256>>>(Wp, Wph, ind * OUTD / 4);
    f2h_kernel<<<(OUTD * OUTD / 4 + 255) / 256, 256>>>(W2, W2h, OUTD * OUTD / 4);

    int aggBlocks = (n * 32 + 255) / 256;
    dim3 gg((n + GBM - 1) / GBM, OUTD / GBN);

    // 3. agg_x: A_hat @ X  (128 cols, single pass)
    aggregate_kernel<<<aggBlocks, 256>>>(xh, axh, n, ind, 0);

    // 4. GEMM1: (AX)@W1 + b1, relu -> h1h ; GEMMp: X@Wp + bp -> idenh
    hgemm_kernel<true,  false, true><<<gg, 256>>>(axh, W1h, b1, nullptr, h1h,   n, ind, OUTD);
    hgemm_kernel<false, false, true><<<gg, 256>>>(xh,  Wph, bp, nullptr, idenh, n, ind, OUTD);

    // 5. agg_h1: A_hat @ H1 (256 cols, two passes)
    aggregate_kernel<<<aggBlocks, 256>>>(h1h, ah1, n, OUTD, 0);
    aggregate_kernel<<<aggBlocks, 256>>>(h1h, ah1, n, OUTD, 128);

    // 6. GEMM2: (AH1)@W2 + b2 + iden, relu -> out (fp32)
    hgemm_kernel<true, true, false><<<gg, 256>>>(ah1, W2h, b2, idenh, out, n, OUTD, OUTD);
}

// round 17
// speedup vs baseline: 1.1238x; 1.1238x over previous
#include <cuda_runtime.h>
#include <cuda_fp16.h>
#include <stdint.h>

#define MAXN 100000
#define MAXE 1600000
#define PAD  64
#define OUTD 256
#define MAXIN 128

// ---------------- scratch (device globals; no runtime allocation) ----------------
__device__ int    g_cnt[MAXN];
__device__ int    g_csr[(size_t)MAXN * PAD];
__device__ float  g_csrw[(size_t)MAXN * PAD];    // precomputed edge weights dinv[s]*dinv[d]
__device__ float  g_dinv[MAXN];
__device__ __half g_xh[(size_t)MAXN * MAXIN];    // fp16 copy of x
__device__ __half g_axh[(size_t)MAXN * MAXIN];   // A_hat @ X (fp16)
__device__ __half g_h1h[(size_t)MAXN * OUTD];    // relu((AX)W1 + b1)
__device__ __half g_xwh[(size_t)MAXN * OUTD];    // H1 @ W2 (gather operand, layer 2)
__device__ __half g_idenh[(size_t)MAXN * OUTD];  // X@Wp + bp
__device__ __half g_W1h[MAXIN * OUTD];
__device__ __half g_W2h[OUTD * OUTD];
__device__ __half g_Wph[MAXIN * OUTD];

// ---------------- small setup kernels ----------------
__global__ void zero_cnt_kernel(int n) {
    int i = blockIdx.x * blockDim.x + threadIdx.x;
    if (i < n) g_cnt[i] = 0;
}

__global__ void f2h_kernel(const float* __restrict__ src, __half* __restrict__ dst, int count4) {
    int i = blockIdx.x * blockDim.x + threadIdx.x;
    if (i < count4) {
        float4 v = *(const float4*)(src + 4 * (size_t)i);
        __half2 h0 = __floats2half2_rn(v.x, v.y);
        __half2 h1 = __floats2half2_rn(v.z, v.w);
        uint2 u; u.x = *(unsigned*)&h0; u.y = *(unsigned*)&h1;
        *(uint2*)(dst + 4 * (size_t)i) = u;
    }
}

// Build padded CSR grouped by destination. int64 vs int32 detection: if data is
// int64 the high dword of every 8-byte word is 0 (values < N); if int32 the high
// dwords contain edge entries (nonzero across 16 words w.h.p.).
__global__ void fill_csr_kernel(const void* __restrict__ edge, int E) {
    const unsigned long long* p64 = (const unsigned long long*)edge;
    unsigned long long hi = 0ull;
#pragma unroll
    for (int i = 0; i < 16; i++) hi |= (p64[i] >> 32);
    const bool is64 = (hi == 0ull);
    const long long* e64 = (const long long*)edge;
    const int*       e32 = (const int*)edge;

    for (int e = blockIdx.x * blockDim.x + threadIdx.x; e < E;
         e += gridDim.x * blockDim.x) {
        int s, d;
        if (is64) { s = (int)e64[e]; d = (int)e64[e + E]; }
        else      { s = e32[e];      d = e32[e + E]; }
        int slot = atomicAdd(&g_cnt[d], 1);
        if (slot < PAD) g_csr[(size_t)d * PAD + slot] = s;
    }
}

__global__ void dinv_kernel(int n) {
    int i = blockIdx.x * blockDim.x + threadIdx.x;
    if (i < n) g_dinv[i] = rsqrtf((float)(g_cnt[i] + 1));  // +1 self-loop
}

// Precompute per-edge normalization weights (one warp per node).
__global__ void csrw_kernel(int n) {
    int w    = (blockIdx.x * blockDim.x + threadIdx.x) >> 5;
    int lane = threadIdx.x & 31;
    if (w >= n) return;
    float di = g_dinv[w];
    int c = g_cnt[w];
    if (c > PAD) c = PAD;
    const int* ep = g_csr + (size_t)w * PAD;
#pragma unroll
    for (int r = 0; r < PAD / 32; r++) {
        int j = r * 32 + lane;
        if (j < c) g_csrw[(size_t)w * PAD + j] = g_dinv[ep[j]] * di;
    }
}

// ---------------- HGEMM via mma.sync: C = A[M,K] @ B[K,N], fp16 in, fp32 accum ----
#define GBM 128
#define GBN 64
#define GBK 32
#define A_STRIDE 40   // halfs per As row (32 + 8 pad)
#define B_STRIDE 72   // halfs per Bs row (64 + 8 pad)

template <bool RELU, bool HALF_OUT>
__global__ __launch_bounds__(256, 2)
void hgemm_kernel(const __half* __restrict__ A, const __half* __restrict__ B,
                  const float* __restrict__ bias, void* __restrict__ Cv,
                  int M, int K, int N) {
    __shared__ __half As[GBM][A_STRIDE];
    __shared__ __half Bs[GBK][B_STRIDE];

    const int tid  = threadIdx.x;
    const int wid  = tid >> 5;
    const int lane = tid & 31;
    const int warpM = wid & 3;
    const int warpN = wid >> 2;
    const int rowBase = blockIdx.x * GBM;
    const int colBase = blockIdx.y * GBN;

    const int arow = tid >> 1;
    const int acg  = (tid & 1) * 16;
    const int brow = tid >> 3;
    const int bcg  = (tid & 7) * 8;

    const bool aok = (rowBase + arow) < M;
    const __half* Ap = A + (size_t)(rowBase + arow) * K + acg;

    const uint4 z4 = make_uint4(0, 0, 0, 0);
    uint4 pa0 = aok ? *(const uint4*)Ap       : z4;
    uint4 pa1 = aok ? *(const uint4*)(Ap + 8) : z4;
    uint4 pb0 = *(const uint4*)(B + (size_t)brow * N + colBase + bcg);

    float acc[2][4][4];
#pragma unroll
    for (int i = 0; i < 2; i++)
#pragma unroll
        for (int j = 0; j < 4; j++)
#pragma unroll
            for (int k = 0; k < 4; k++) acc[i][j][k] = 0.f;

    const uint32_t AsU = (uint32_t)__cvta_generic_to_shared(&As[0][0]);
    const uint32_t BsU = (uint32_t)__cvta_generic_to_shared(&Bs[0][0]);
    const uint32_t aLaneOff = (lane & 15) * (A_STRIDE * 2) + (lane >> 4) * 16;
    const uint32_t bLaneOff = (lane & 15) * (B_STRIDE * 2) + (lane >> 4) * 16;

    int k0 = 0;
    while (true) {
        *(uint4*)&As[arow][acg]     = pa0;
        *(uint4*)&As[arow][acg + 8] = pa1;
        *(uint4*)&Bs[brow][bcg]     = pb0;
        __syncthreads();

        k0 += GBK;
        const bool more = (k0 < K);
        if (more) {
            pa0 = aok ? *(const uint4*)(Ap + k0)     : z4;
            pa1 = aok ? *(const uint4*)(Ap + k0 + 8) : z4;
            pb0 = *(const uint4*)(B + (size_t)(k0 + brow) * N + colBase + bcg);
        }

#pragma unroll
        for (int ks = 0; ks < 2; ks++) {
            uint32_t a[2][4];
#pragma unroll
            for (int mi = 0; mi < 2; mi++) {
                uint32_t addr = AsU + (warpM * 32 + mi * 16) * (A_STRIDE * 2)
                              + ks * 32 + aLaneOff;
                asm volatile("ldmatrix.sync.aligned.m8n8.x4.shared.b16 {%0,%1,%2,%3}, [%4];"
                             : "=r"(a[mi][0]), "=r"(a[mi][1]), "=r"(a[mi][2]), "=r"(a[mi][3])
                             : "r"(addr));
            }
            uint32_t b[4][2];
#pragma unroll
            for (int np = 0; np < 2; np++) {
                uint32_t addr = BsU + (ks * 16) * (B_STRIDE * 2)
                              + (warpN * 32 + np * 16) * 2 + bLaneOff;
                uint32_t r0, r1, r2, r3;
                asm volatile("ldmatrix.sync.aligned.m8n8.x4.trans.shared.b16 {%0,%1,%2,%3}, [%4];"
                             : "=r"(r0), "=r"(r1), "=r"(r2), "=r"(r3)
                             : "r"(addr));
                b[np * 2][0] = r0; b[np * 2][1] = r1;
                b[np * 2 + 1][0] = r2; b[np * 2 + 1][1] = r3;
            }
#pragma unroll
            for (int mi = 0; mi < 2; mi++)
#pragma unroll
                for (int nt = 0; nt < 4; nt++) {
                    asm volatile(
                        "mma.sync.aligned.m16n8k16.row.col.f32.f16.f16.f32 "
                        "{%0,%1,%2,%3}, {%4,%5,%6,%7}, {%8,%9}, {%0,%1,%2,%3};"
                        : "+f"(acc[mi][nt][0]), "+f"(acc[mi][nt][1]),
                          "+f"(acc[mi][nt][2]), "+f"(acc[mi][nt][3])
                        : "r"(a[mi][0]), "r"(a[mi][1]), "r"(a[mi][2]), "r"(a[mi][3]),
                          "r"(b[nt][0]), "r"(b[nt][1]));
                }
        }

        if (!more) break;
        __syncthreads();
    }

    const int group = lane >> 2;
    const int tid4  = lane & 3;
#pragma unroll
    for (int mi = 0; mi < 2; mi++) {
#pragma unroll
        for (int nt = 0; nt < 4; nt++) {
            int col = colBase + warpN * 32 + nt * 8 + tid4 * 2;
            float bx = 0.f, by = 0.f;
            if (bias) { bx = bias[col]; by = bias[col + 1]; }
#pragma unroll
            for (int rh = 0; rh < 2; rh++) {
                int r = rowBase + warpM * 32 + mi * 16 + group + rh * 8;
                if (r >= M) continue;
                float v0 = acc[mi][nt][rh * 2 + 0] + bx;
                float v1 = acc[mi][nt][rh * 2 + 1] + by;
                if (RELU) { v0 = fmaxf(v0, 0.f); v1 = fmaxf(v1, 0.f); }
                if (HALF_OUT) {
                    __half2 h = __floats2half2_rn(v0, v1);
                    *(__half2*)((__half*)Cv + (size_t)r * N + col) = h;
                } else {
                    *(float2*)((float*)Cv + (size_t)r * N + col) = make_float2(v0, v1);
                }
            }
        }
    }
}

// ---------------- aggregation: one warp per node, precomputed weights ----------------
// FUSED: adds bias + fp16 residual + relu, writes fp32; else pure fp16 out.
// colOff selects a 128-col slice of a `pitch`-wide matrix.
__device__ __forceinline__ void h4_acc(uint2 v, float w, float* acc) {
    float2 f0 = __half22float2(*(__half2*)&v.x);
    float2 f1 = __half22float2(*(__half2*)&v.y);
    acc[0] = fmaf(w, f0.x, acc[0]); acc[1] = fmaf(w, f0.y, acc[1]);
    acc[2] = fmaf(w, f1.x, acc[2]); acc[3] = fmaf(w, f1.y, acc[3]);
}

template <bool FUSED>
__global__ __launch_bounds__(256)
void aggregate_kernel(const __half* __restrict__ src,
                      const float* __restrict__ bias,      // FUSED only
                      const __half* __restrict__ resid,    // FUSED only
                      void* __restrict__ outv,
                      int n, int pitch, int colOff) {
    __shared__ int   shI[8][PAD + 1];
    __shared__ float shW[8][PAD + 1];

    const int wslot = threadIdx.x >> 5;
    const int w     = (blockIdx.x * blockDim.x + threadIdx.x) >> 5;
    const int lane  = threadIdx.x & 31;
    if (w >= n) return;

    const int col = colOff + lane * 4;

    int c = g_cnt[w];
    if (c > PAD) c = PAD;

    // coalesced metadata fetch (indices + precomputed weights); append self-loop
    const int*   ep = g_csr  + (size_t)w * PAD;
    const float* wp = g_csrw + (size_t)w * PAD;
#pragma unroll
    for (int r = 0; r < PAD / 32; r++) {
        int j = r * 32 + lane;
        if (j < c) {
            shI[wslot][j] = ep[j];
            shW[wslot][j] = wp[j];
        }
    }
    if (lane == 0) {
        float di = g_dinv[w];
        shI[wslot][c] = w;
        shW[wslot][c] = di * di;
    }
    __syncwarp();
    const int tot = c + 1;

    float acc[4] = {0.f, 0.f, 0.f, 0.f};
    const int*   shi = shI[wslot];
    const float* shw = shW[wslot];

    int j = 0;
    for (; j + 4 <= tot; j += 4) {
        int   s0 = shi[j],   s1 = shi[j+1], s2 = shi[j+2], s3 = shi[j+3];
        float w0 = shw[j],   w1 = shw[j+1], w2 = shw[j+2], w3 = shw[j+3];
        uint2 v0 = *(const uint2*)(src + (size_t)s0 * pitch + col);
        uint2 v1 = *(const uint2*)(src + (size_t)s1 * pitch + col);
        uint2 v2 = *(const uint2*)(src + (size_t)s2 * pitch + col);
        uint2 v3 = *(const uint2*)(src + (size_t)s3 * pitch + col);
        h4_acc(v0, w0, acc); h4_acc(v1, w1, acc);
        h4_acc(v2, w2, acc); h4_acc(v3, w3, acc);
    }
    for (; j < tot; j++) {
        uint2 v = *(const uint2*)(src + (size_t)shi[j] * pitch + col);
        h4_acc(v, shw[j], acc);
    }

    if (FUSED) {
        float4 b = *(const float4*)(bias + col);
        acc[0] += b.x; acc[1] += b.y; acc[2] += b.z; acc[3] += b.w;
        uint2 q = *(const uint2*)(resid + (size_t)w * pitch + col);
        float2 f0 = __half22float2(*(__half2*)&q.x);
        float2 f1 = __half22float2(*(__half2*)&q.y);
        acc[0] += f0.x; acc[1] += f0.y; acc[2] += f1.x; acc[3] += f1.y;
#pragma unroll
        for (int k = 0; k < 4; k++) acc[k] = fmaxf(acc[k], 0.f);
        float* o = (float*)outv;
        *(float4*)(o + (size_t)w * pitch + col) = make_float4(acc[0], acc[1], acc[2], acc[3]);
    } else {
        __half2 h01 = __floats2half2_rn(acc[0], acc[1]);
        __half2 h23 = __floats2half2_rn(acc[2], acc[3]);
        uint2 u; u.x = *(unsigned*)&h01; u.y = *(unsigned*)&h23;
        __half* o = (__half*)outv;
        *(uint2*)(o + (size_t)w * pitch + col) = u;
    }
}

// ---------------- launch ----------------
extern "C" void kernel_launch(void* const* d_in, const int* in_sizes, int n_in,
                              void* d_out, int out_size) {
    const float* x  = (const float*)d_in[0];
    const void*  ei = d_in[1];
    const float* W1 = (const float*)d_in[2];
    const float* b1 = (const float*)d_in[3];
    const float* W2 = (const float*)d_in[4];
    const float* b2 = (const float*)d_in[5];
    const float* Wp = (const float*)d_in[6];
    const float* bp = (const float*)d_in[7];
    float* out = (float*)d_out;

    int ind = in_sizes[2] / OUTD;     // W1 is [IN, 256]
    int n   = in_sizes[0] / ind;      // nodes
    int E   = in_sizes[1] / 2;        // edges
    if (n > MAXN) n = MAXN;
    if (E > MAXE) E = MAXE;

    __half *xh, *axh, *h1h, *xwh, *idenh, *W1h, *W2h, *Wph;
    cudaGetSymbolAddress((void**)&xh,    g_xh);
    cudaGetSymbolAddress((void**)&axh,   g_axh);
    cudaGetSymbolAddress((void**)&h1h,   g_h1h);
    cudaGetSymbolAddress((void**)&xwh,   g_xwh);
    cudaGetSymbolAddress((void**)&idenh, g_idenh);
    cudaGetSymbolAddress((void**)&W1h,   g_W1h);
    cudaGetSymbolAddress((void**)&W2h,   g_W2h);
    cudaGetSymbolAddress((void**)&Wph,   g_Wph);

    // 1. build padded CSR + degrees + precomputed edge weights
    zero_cnt_kernel<<<(n + 255) / 256, 256>>>(n);
    fill_csr_kernel<<<(E + 255) / 256, 256>>>(ei, E);
    dinv_kernel<<<(n + 255) / 256, 256>>>(n);
    int warpGrid = (n * 32 + 255) / 256;
    csrw_kernel<<<warpGrid, 256>>>(n);

    // 2. fp32 -> fp16 converts
    int xc4 = (n * ind) / 4;
    f2h_kernel<<<(xc4 + 255) / 256, 256>>>(x, xh, xc4);
    f2h_kernel<<<(ind * OUTD / 4 + 255) / 256, 256>>>(W1, W1h, ind * OUTD / 4);
    f2h_kernel<<<(ind * OUTD / 4 + 255) / 256, 256>>>(Wp, Wph, ind * OUTD / 4);
    f2h_kernel<<<(OUTD * OUTD / 4 + 255) / 256, 256>>>(W2, W2h, OUTD * OUTD / 4);

    dim3 gg((n + GBM - 1) / GBM, OUTD / GBN);

    // 3. layer 1, agg-first: axh = A_hat @ X (single 128-col pass)
    aggregate_kernel<false><<<warpGrid, 256>>>(xh, nullptr, nullptr, axh, n, ind, 0);

    // 4. GEMM1: (AX)@W1 + b1, relu -> h1h ; GEMMp: X@Wp + bp -> idenh
    hgemm_kernel<true,  true><<<gg, 256>>>(axh, W1h, b1, h1h,   n, ind, OUTD);
    hgemm_kernel<false, true><<<gg, 256>>>(xh,  Wph, bp, idenh, n, ind, OUTD);

    // 5. GEMM2: H1@W2 -> xwh (raw)
    hgemm_kernel<false, true><<<gg, 256>>>(h1h, W2h, nullptr, xwh, n, OUTD, OUTD);

    // 6. layer 2, agg-last fused: out = relu(A_hat@(H1W2) + b2 + iden), two passes
    aggregate_kernel<true><<<warpGrid, 256>>>(xwh, b2, idenh, out, n, OUTD, 0);
    aggregate_kernel<true><<<warpGrid, 256>>>(xwh, b2, idenh, out, n, OUTD, 128);
}